// round 4
// baseline (speedup 1.0000x reference)
#include <cuda_runtime.h>
#include <math.h>

#define BB 2
#define NN 8192
#define NPT (BB*NN)
#define KNN 10
#define GRID 16
#define GC (GRID*GRID*GRID)
#define HCELL 0.0625f
#define NBLK 128
#define NTHR 512

// ---------------- device scratch ----------------
__device__ float4 g_sp4[NPT];        // sorted points (x,y,z, sq with sign bit = mask)
__device__ int    g_sidx[NPT];       // sorted -> original index
__device__ int    g_cnt[BB*GC];
__device__ int2   g_range[BB*GC];    // (start,end) within batch
__device__ int    g_cur[BB*GC];
__device__ double g_cacc[BB][4];     // masked centroid sums + count
__device__ float  g_geom[NPT * 6];
__device__ int    g_mtype;
__device__ float  g_T;
__device__ unsigned g_barcnt = 0;    // grid barrier
__device__ unsigned g_sense  = 0;

// ---------------- grid barrier (128 co-resident blocks) ----------------
__device__ __forceinline__ void gridbar() {
    __syncthreads();
    if (threadIdx.x == 0) {
        __threadfence();
        unsigned gen = atomicAdd(&g_sense, 0u);
        if (atomicAdd(&g_barcnt, 1u) == NBLK - 1) {
            g_barcnt = 0;
            __threadfence();
            atomicAdd(&g_sense, 1u);
        } else {
            while (atomicAdd(&g_sense, 0u) == gen) {}
        }
        __threadfence();
    }
    __syncthreads();
}

// ---------------- f32x2 helpers ----------------
#define FMA2(d, a, b) asm("fma.rn.f32x2 %0, %1, %2, %3;" : "=l"(d) : "l"(a), "l"(b), "l"(d))
__device__ __forceinline__ unsigned long long pack2(float v) {
    unsigned long long r; unsigned u = __float_as_uint(v);
    asm("mov.b64 %0, {%1, %1};" : "=l"(r) : "r"(u));
    return r;
}
__device__ __forceinline__ void unpack2(unsigned long long v, float& lo, float& hi) {
    unsigned a, b;
    asm("mov.b64 {%0, %1}, %2;" : "=r"(a), "=r"(b) : "l"(v));
    lo = __uint_as_float(a); hi = __uint_as_float(b);
}

__device__ __forceinline__ int cell_of(float x, float y, float z) {
    int cx = min(GRID - 1, max(0, (int)(x * (float)GRID)));
    int cy = min(GRID - 1, max(0, (int)(y * (float)GRID)));
    int cz = min(GRID - 1, max(0, (int)(z * (float)GRID)));
    return (cz * GRID + cy) * GRID + cx;
}

__device__ __forceinline__ bool read_mask(const void* mp, int i, int mt) {
    if (mt & 1) return ((const unsigned char*)mp)[i] != 0;
    if (mt & 2) return ((const float*)mp)[i] != 0.0f;
    return ((const int*)mp)[i] != 0;
}

// ---------------- analytic eigenvalues of symmetric 3x3 (fp64) ----------------
__device__ __forceinline__ float curv_from_cov(float c00, float c01, float c02,
                                               float c11, float c12, float c22) {
    double a00 = c00, a01 = c01, a02 = c02, a11 = c11, a12 = c12, a22 = c22;
    double p1 = a01 * a01 + a02 * a02 + a12 * a12;
    double q  = (a00 + a11 + a22) / 3.0;
    double d0 = a00 - q, d1 = a11 - q, d2v = a22 - q;
    double p2 = d0 * d0 + d1 * d1 + d2v * d2v + 2.0 * p1;
    double emin, emax;
    if (!(p2 > 0.0)) { emin = q; emax = q; }
    else {
        double p = sqrt(p2 / 6.0);
        double ip = 1.0 / p;
        double b00 = d0 * ip, b11 = d1 * ip, b22 = d2v * ip;
        double b01 = a01 * ip, b02 = a02 * ip, b12 = a12 * ip;
        double detB = b00 * (b11 * b22 - b12 * b12)
                    - b01 * (b01 * b22 - b12 * b02)
                    + b02 * (b01 * b12 - b11 * b02);
        double r = 0.5 * detB;
        r = fmin(1.0, fmax(-1.0, r));
        double phi = acos(r) / 3.0;
        emax = q + 2.0 * p * cos(phi);
        emin = q + 2.0 * p * cos(phi + 2.0943951023931953);
    }
    float e0 = (float)emin, e2 = (float)emax;
    return e0 / (e2 + 1e-8f);
}

// ---------------- per-lane candidate scan ----------------
__device__ __forceinline__ void scan_range(int2 rg, int boff, float pix, float piy,
                                           float piz, float piw, float Tloc,
                                           unsigned long long (&best)[KNN], int& cnt) {
    for (int j = rg.x; j < rg.y; ++j) {
        float4 pj = g_sp4[boff + j];
        float sqj = fabsf(pj.w);
        float Tv  = (__float_as_uint(pj.w) & 0x80000000u) ? Tloc : __int_as_float(0xff800000);
        float dot = fmaf(pix, pj.x, fmaf(piy, pj.y, piz * pj.z));
        float d2  = fmaf(-2.0f, dot, piw + sqj);
        if (d2 <= Tv) cnt++;
        float d2c = fmaxf(d2, 0.0f);
        unsigned long long key =
            ((unsigned long long)__float_as_uint(d2c) << 32) | (unsigned)j;
        if (key < best[KNN - 1]) {
#pragma unroll
            for (int k = 0; k < KNN; k++) {
                if (key < best[k]) {
                    unsigned long long tmp = best[k]; best[k] = key; key = tmp;
                }
            }
        }
    }
}

// ================= THE fused persistent kernel =================
__global__ void __launch_bounds__(NTHR, 1)
k_fused(const float* __restrict__ pts, const float* __restrict__ feat,
        const void* __restrict__ mask,
        const float* __restrict__ W1, const float* __restrict__ b1,
        const float* __restrict__ W2, const float* __restrict__ b2,
        float* __restrict__ out) {
    extern __shared__ float sm[];
    float* sW1 = sm;             // 70*128   = 8960
    float* sB1 = sm + 8960;      // 128
    float* sW2 = sm + 9088;      // 128*128  = 16384
    float* sB2 = sm + 25472;     // 128
    float* sX  = sm + 25600;     // 128*72   = 9216
    float* sH  = sm + 34816;     // 128*132  = 16896 (total 51712 fl = 206848 B)

    const int tid = threadIdx.x;
    const int bid = blockIdx.x;
    const int gid = bid * NTHR + tid;

    // ---------- phase 0: init + weight preload ----------
    for (int i = gid; i < BB * GC; i += NBLK * NTHR) g_cnt[i] = 0;
    if (gid == 0) {
        for (int b = 0; b < BB; b++)
            for (int c = 0; c < 4; c++) g_cacc[b][c] = 0.0;
        g_mtype = 0;
        const float R = 0.02f;
        float t = __fmul_rn(R, R);
        while (__fsqrt_rn(t) >= R) t = __uint_as_float(__float_as_uint(t) - 1u);
        for (;;) {
            float nt = __uint_as_float(__float_as_uint(t) + 1u);
            if (__fsqrt_rn(nt) < R) t = nt; else break;
        }
        g_T = t;
    }
    for (int i = tid; i < 8960;  i += NTHR) sW1[i] = W1[i];
    for (int i = tid; i < 16384; i += NTHR) sW2[i] = W2[i];
    if (tid < 128) { sB1[tid] = b1[tid]; sB2[tid] = b2[tid]; }
    gridbar();

    // ---------- phase 1: cell counts + mask dtype detect ----------
    {
        bool act = gid < NPT;
        float x = 0, y = 0, z = 0; unsigned char mb = 0;
        if (act) {
            x = pts[gid * 3 + 0]; y = pts[gid * 3 + 1]; z = pts[gid * 3 + 2];
            mb = ((const unsigned char*)mask)[gid];
            atomicAdd(&g_cnt[(gid / NN) * GC + cell_of(x, y, z)], 1);
        }
        int r = gid & 3;
        unsigned m1 = __ballot_sync(0xFFFFFFFFu, act && (r == 1) && mb);
        unsigned m2 = __ballot_sync(0xFFFFFFFFu, act && (r >= 2) && mb);
        if ((tid & 31) == 0 && (m1 | m2))
            atomicOr(&g_mtype, (m1 ? 1 : 0) | (m2 ? 2 : 0));
    }
    gridbar();

    // ---------- phase 2: per-batch exclusive scan (blocks 0,1) ----------
    if (bid < BB) {
        int* part = (int*)sH;                    // reuse sH (free until phase 5)
        int base = bid * GC + tid * 8;
        int loc[8]; int s = 0;
#pragma unroll
        for (int k = 0; k < 8; k++) { loc[k] = s; s += g_cnt[base + k]; }
        part[tid] = s;
        __syncthreads();
        for (int d = 1; d < NTHR; d <<= 1) {
            int v = (tid >= d) ? part[tid - d] : 0;
            __syncthreads();
            part[tid] += v;
            __syncthreads();
        }
        int off = part[tid] - s;
#pragma unroll
        for (int k = 0; k < 8; k++) {
            int st = off + loc[k];
            g_range[base + k] = make_int2(st, st + g_cnt[base + k]);
            g_cur[base + k]   = st;
        }
    }
    gridbar();

    // ---------- phase 3: scatter + masked centroid ----------
    if (gid < NPT) {
        int mt = g_mtype;
        float x = pts[gid * 3 + 0], y = pts[gid * 3 + 1], z = pts[gid * 3 + 2];
        float sq = __fadd_rn(__fadd_rn(__fmul_rn(x, x), __fmul_rn(y, y)), __fmul_rn(z, z));
        int b = gid / NN;
        int cell = b * GC + cell_of(x, y, z);
        bool mk = read_mask(mask, gid, mt);
        float wv = mk ? __uint_as_float(__float_as_uint(sq) | 0x80000000u) : sq;
        int pos = atomicAdd(&g_cur[cell], 1);
        int dst = b * NN + pos;
        g_sp4[dst]  = make_float4(x, y, z, wv);
        g_sidx[dst] = gid;
        double vx = mk ? (double)x : 0.0, vy = mk ? (double)y : 0.0;
        double vz = mk ? (double)z : 0.0, vc = mk ? 1.0 : 0.0;
#pragma unroll
        for (int o = 16; o > 0; o >>= 1) {
            vx += __shfl_down_sync(0xFFFFFFFFu, vx, o);
            vy += __shfl_down_sync(0xFFFFFFFFu, vy, o);
            vz += __shfl_down_sync(0xFFFFFFFFu, vz, o);
            vc += __shfl_down_sync(0xFFFFFFFFu, vc, o);
        }
        if ((tid & 31) == 0) {
            atomicAdd(&g_cacc[b][0], vx);
            atomicAdd(&g_cacc[b][1], vy);
            atomicAdd(&g_cacc[b][2], vz);
            atomicAdd(&g_cacc[b][3], vc);
        }
    }
    gridbar();

    // ---------- phase 4: 8-lane cooperative exact 10-NN + density ----------
    {
        const unsigned gmask = 0xFFu << ((tid & 31) & ~7);  // this 8-lane group
        const float Tloc = g_T;
#pragma unroll 1
        for (int it = 0; it < 2; it++) {
            int task = gid + it * (NBLK * NTHR);
            int p  = task >> 3;
            int l8 = task & 7;
            int b  = p >> 13;
            int s  = p & (NN - 1);
            int boff  = b * NN;
            int cbase = b * GC;

            float4 pi = g_sp4[boff + s];
            float pix = pi.x, piy = pi.y, piz = pi.z, piw = fabsf(pi.w);
            int orig  = g_sidx[boff + s];

            int cix = min(GRID - 1, max(0, (int)(pix * (float)GRID)));
            int ciy = min(GRID - 1, max(0, (int)(piy * (float)GRID)));
            int ciz = min(GRID - 1, max(0, (int)(piz * (float)GRID)));

            unsigned long long best[KNN];
            int cnt;
            float c00, c01, c02, c11, c12, c22;
            unsigned long long d10key;

            for (int R = 2;; R++) {
#pragma unroll
                for (int k = 0; k < KNN; k++) best[k] = 0xFFFFFFFFFFFFFFFFull;
                cnt = 0;
                c00 = c01 = c02 = c11 = c12 = c22 = 0.0f;

                if (R == 2) {
#pragma unroll 4
                    for (int idx = l8; idx < 125; idx += 8) {
                        int dz = idx / 25, rem = idx - dz * 25;
                        int dy = rem / 5,  dx  = rem - dy * 5;
                        int zz = ciz + dz - 2, yy = ciy + dy - 2, xx = cix + dx - 2;
                        if ((unsigned)zz < GRID && (unsigned)yy < GRID && (unsigned)xx < GRID) {
                            int2 rg = g_range[cbase + (zz * GRID + yy) * GRID + xx];
                            scan_range(rg, boff, pix, piy, piz, piw, Tloc, best, cnt);
                        }
                    }
                } else {
                    int c = 0;
                    for (int zz = ciz - R; zz <= ciz + R; zz++)
                        for (int yy = ciy - R; yy <= ciy + R; yy++)
                            for (int xx = cix - R; xx <= cix + R; xx++) {
                                if ((c++ & 7) == l8 &&
                                    (unsigned)zz < GRID && (unsigned)yy < GRID && (unsigned)xx < GRID) {
                                    int2 rg = g_range[cbase + (zz * GRID + yy) * GRID + xx];
                                    scan_range(rg, boff, pix, piy, piz, piw, Tloc, best, cnt);
                                }
                            }
                }

                // 10-round merge across the 8 lanes; owner pops + accumulates cov
                d10key = 0xFFFFFFFFFFFFFFFFull;
#pragma unroll
                for (int round = 0; round < KNN; round++) {
                    unsigned long long m = best[0];
                    m = min(m, __shfl_xor_sync(gmask, m, 1));
                    m = min(m, __shfl_xor_sync(gmask, m, 2));
                    m = min(m, __shfl_xor_sync(gmask, m, 4));
                    if (m == best[0] && m != 0xFFFFFFFFFFFFFFFFull) {
                        int j = (int)(unsigned)(m & 0xFFFFFFFFull);
                        float4 q = g_sp4[boff + j];
                        float dx = q.x - pix, dy = q.y - piy, dz = q.z - piz;
                        c00 = fmaf(dx, dx, c00); c01 = fmaf(dx, dy, c01); c02 = fmaf(dx, dz, c02);
                        c11 = fmaf(dy, dy, c11); c12 = fmaf(dy, dz, c12); c22 = fmaf(dz, dz, c22);
#pragma unroll
                        for (int k = 0; k < KNN - 1; k++) best[k] = best[k + 1];
                        best[KNN - 1] = 0xFFFFFFFFFFFFFFFFull;
                    }
                    d10key = m;
                }

                // exactness bound: distance to scanned-box walls (domain edges free)
                float g = __int_as_float(0x7f800000);
                if (cix - R > 0)        g = fminf(g, pix - (float)(cix - R) * HCELL);
                if (cix + R < GRID - 1) g = fminf(g, (float)(cix + R + 1) * HCELL - pix);
                if (ciy - R > 0)        g = fminf(g, piy - (float)(ciy - R) * HCELL);
                if (ciy + R < GRID - 1) g = fminf(g, (float)(ciy + R + 1) * HCELL - piy);
                if (ciz - R > 0)        g = fminf(g, piz - (float)(ciz - R) * HCELL);
                if (ciz + R < GRID - 1) g = fminf(g, (float)(ciz + R + 1) * HCELL - piz);
                float d10 = __uint_as_float((unsigned)(d10key >> 32));
                if (d10 < g * g) break;
            }

            // reduce density + covariance across the 8 lanes
#pragma unroll
            for (int o = 1; o < 8; o <<= 1) {
                cnt += __shfl_xor_sync(gmask, cnt, o);
                c00 += __shfl_xor_sync(gmask, c00, o);
                c01 += __shfl_xor_sync(gmask, c01, o);
                c02 += __shfl_xor_sync(gmask, c02, o);
                c11 += __shfl_xor_sync(gmask, c11, o);
                c12 += __shfl_xor_sync(gmask, c12, o);
                c22 += __shfl_xor_sync(gmask, c22, o);
            }

            if (l8 == 0) {
                c00 = __fdiv_rn(c00, 10.0f); c01 = __fdiv_rn(c01, 10.0f); c02 = __fdiv_rn(c02, 10.0f);
                c11 = __fdiv_rn(c11, 10.0f); c12 = __fdiv_rn(c12, 10.0f); c22 = __fdiv_rn(c22, 10.0f);
                float curv = curv_from_cov(c00, c01, c02, c11, c12, c22);

                double cm   = g_cacc[b][3];
                double cden = cm > 1.0 ? cm : 1.0;
                float cx = (float)(g_cacc[b][0] / cden);
                float cy = (float)(g_cacc[b][1] / cden);
                float cz = (float)(g_cacc[b][2] / cden);
                float rx = pix - cx, ry = piy - cy, rz = piz - cz;
                float distc = __fsqrt_rn(__fadd_rn(__fadd_rn(__fmul_rn(rx, rx), __fmul_rn(ry, ry)), __fmul_rn(rz, rz)));
                float horiz = __fsqrt_rn(__fadd_rn(__fmul_rn(rx, rx), __fmul_rn(ry, ry)));
                float rad   = atan2f(ry, rx);

                bool valid = cm > 0.0;
                g_geom[orig * 6 + 0] = valid ? distc : 0.0f;
                g_geom[orig * 6 + 1] = valid ? rz    : 0.0f;
                g_geom[orig * 6 + 2] = valid ? horiz : 0.0f;
                g_geom[orig * 6 + 3] = valid ? (float)cnt : 0.0f;
                g_geom[orig * 6 + 4] = valid ? curv  : 0.0f;
                g_geom[orig * 6 + 5] = valid ? rad   : 0.0f;
            }
        }
    }
    gridbar();

    // ---------- phase 5: fused 2-layer MLP (f32x2 FMA) ----------
    {
        int m0 = bid * 128;
        for (int i = tid; i < 128 * 64; i += NTHR) {
            int r = i >> 6, c = i & 63;
            sX[r * 72 + c] = feat[(m0 + r) * 64 + c];
        }
        for (int i = tid; i < 128 * 6; i += NTHR) {
            int r = i / 6, c = i % 6;
            sX[r * 72 + 64 + c] = g_geom[(m0 + r) * 6 + c];
        }
        __syncthreads();

        int cg = tid & 31;     // cols cg*4 .. cg*4+3
        int rg = tid >> 5;     // rows rg*8 .. rg*8+7

        unsigned long long acc[8][2];
#pragma unroll
        for (int r = 0; r < 8; r++) { acc[r][0] = 0ull; acc[r][1] = 0ull; }

        for (int k = 0; k < 70; k++) {
            ulonglong2 w2 = *(const ulonglong2*)(sW1 + k * 128 + cg * 4);
#pragma unroll
            for (int r = 0; r < 8; r++) {
                unsigned long long xp = pack2(sX[(rg * 8 + r) * 72 + k]);
                FMA2(acc[r][0], w2.x, xp);
                FMA2(acc[r][1], w2.y, xp);
            }
        }
        {
            float4 bv = *(const float4*)(sB1 + cg * 4);
#pragma unroll
            for (int r = 0; r < 8; r++) {
                float a0, a1, a2, a3;
                unpack2(acc[r][0], a0, a1);
                unpack2(acc[r][1], a2, a3);
                float4 h;
                h.x = fmaxf(a0 + bv.x, 0.0f);
                h.y = fmaxf(a1 + bv.y, 0.0f);
                h.z = fmaxf(a2 + bv.z, 0.0f);
                h.w = fmaxf(a3 + bv.w, 0.0f);
                *(float4*)(sH + (rg * 8 + r) * 132 + cg * 4) = h;
            }
        }
        __syncthreads();

#pragma unroll
        for (int r = 0; r < 8; r++) { acc[r][0] = 0ull; acc[r][1] = 0ull; }

        for (int k = 0; k < 128; k++) {
            ulonglong2 w2 = *(const ulonglong2*)(sW2 + k * 128 + cg * 4);
#pragma unroll
            for (int r = 0; r < 8; r++) {
                unsigned long long hp = pack2(sH[(rg * 8 + r) * 132 + k]);
                FMA2(acc[r][0], w2.x, hp);
                FMA2(acc[r][1], w2.y, hp);
            }
        }
        {
            float4 bv = *(const float4*)(sB2 + cg * 4);
#pragma unroll
            for (int r = 0; r < 8; r++) {
                float a0, a1, a2, a3;
                unpack2(acc[r][0], a0, a1);
                unpack2(acc[r][1], a2, a3);
                float4 o;
                o.x = fmaxf(a0 + bv.x, 0.0f);
                o.y = fmaxf(a1 + bv.y, 0.0f);
                o.z = fmaxf(a2 + bv.z, 0.0f);
                o.w = fmaxf(a3 + bv.w, 0.0f);
                *(float4*)(out + (size_t)(m0 + rg * 8 + r) * 128 + cg * 4) = o;
            }
        }
    }
}

// ---------------- launch ----------------
extern "C" void kernel_launch(void* const* d_in, const int* in_sizes, int n_in,
                              void* d_out, int out_size) {
    const float* points = (const float*)d_in[0];
    const float* feat   = (const float*)d_in[1];
    const void*  mask   = d_in[2];
    const float* W1     = (const float*)d_in[3];
    const float* b1     = (const float*)d_in[4];
    const float* W2     = (const float*)d_in[5];
    const float* b2     = (const float*)d_in[6];
    float* out = (float*)d_out;

    cudaFuncSetAttribute(k_fused, cudaFuncAttributeMaxDynamicSharedMemorySize, 212992);

    k_fused<<<NBLK, NTHR, 206848>>>(points, feat, mask, W1, b1, W2, b2, out);
}

// round 5
// speedup vs baseline: 1.4333x; 1.4333x over previous
#include <cuda_runtime.h>
#include <math.h>

#define BB 2
#define NN 8192
#define NPT (BB*NN)
#define KNN 10
#define GRID 16
#define GC (GRID*GRID*GRID)
#define HCELL 0.0625f
#define NBLKP 128
#define NTHRP 256

// ---------------- device scratch ----------------
__device__ float4 g_sp4[NPT];        // sorted points (x,y,z, sq with sign bit = mask)
__device__ int    g_sidx[NPT];       // sorted -> original index
__device__ int    g_cnt[BB*GC];
__device__ int2   g_range[BB*GC];    // (start,end) within batch
__device__ int    g_cur[BB*GC];
__device__ double g_cacc[BB][4];     // masked centroid sums + count
__device__ float  g_geom[NPT * 6];
__device__ int    g_mtype;
__device__ float  g_T;
__device__ unsigned g_barcnt = 0;
__device__ unsigned g_sense  = 0;

// ---------------- grid barrier (co-resident blocks only) ----------------
__device__ __forceinline__ void gridbar() {
    __syncthreads();
    if (threadIdx.x == 0) {
        __threadfence();
        unsigned gen = atomicAdd(&g_sense, 0u);
        if (atomicAdd(&g_barcnt, 1u) == NBLKP - 1) {
            g_barcnt = 0;
            __threadfence();
            atomicAdd(&g_sense, 1u);
        } else {
            while (atomicAdd(&g_sense, 0u) == gen) {}
        }
        __threadfence();
    }
    __syncthreads();
}

// ---------------- f32x2 helpers ----------------
#define FMA2(d, a, b) asm("fma.rn.f32x2 %0, %1, %2, %3;" : "=l"(d) : "l"(a), "l"(b), "l"(d))
__device__ __forceinline__ unsigned long long pack2(float v) {
    unsigned long long r; unsigned u = __float_as_uint(v);
    asm("mov.b64 %0, {%1, %1};" : "=l"(r) : "r"(u));
    return r;
}
__device__ __forceinline__ void unpack2(unsigned long long v, float& lo, float& hi) {
    unsigned a, b;
    asm("mov.b64 {%0, %1}, %2;" : "=r"(a), "=r"(b) : "l"(v));
    lo = __uint_as_float(a); hi = __uint_as_float(b);
}

__device__ __forceinline__ int cell_of(float x, float y, float z) {
    int cx = min(GRID - 1, max(0, (int)(x * (float)GRID)));
    int cy = min(GRID - 1, max(0, (int)(y * (float)GRID)));
    int cz = min(GRID - 1, max(0, (int)(z * (float)GRID)));
    return (cz * GRID + cy) * GRID + cx;
}

__device__ __forceinline__ bool read_mask(const void* mp, int i, int mt) {
    if (mt & 1) return ((const unsigned char*)mp)[i] != 0;
    if (mt & 2) return ((const float*)mp)[i] != 0.0f;
    return ((const int*)mp)[i] != 0;
}

// ================= kernel 1: prep (init + count + scan + scatter) =================
__global__ void __launch_bounds__(NTHRP)
k_prep(const float* __restrict__ pts, const void* __restrict__ mask) {
    const int tid = threadIdx.x;
    const int bid = blockIdx.x;
    const int gid = bid * NTHRP + tid;

    // phase 0: zero state
    for (int i = gid; i < BB * GC; i += NBLKP * NTHRP) g_cnt[i] = 0;
    if (gid == 0) {
        for (int b = 0; b < BB; b++)
            for (int c = 0; c < 4; c++) g_cacc[b][c] = 0.0;
        g_mtype = 0;
        const float R = 0.02f;
        float t = __fmul_rn(R, R);
        while (__fsqrt_rn(t) >= R) t = __uint_as_float(__float_as_uint(t) - 1u);
        for (;;) {
            float nt = __uint_as_float(__float_as_uint(t) + 1u);
            if (__fsqrt_rn(nt) < R) t = nt; else break;
        }
        g_T = t;
    }
    gridbar();

    // phase 1: cell counts + mask dtype detect
    {
        bool act = gid < NPT;
        unsigned char mb = 0;
        if (act) {
            float x = pts[gid * 3 + 0], y = pts[gid * 3 + 1], z = pts[gid * 3 + 2];
            mb = ((const unsigned char*)mask)[gid];
            atomicAdd(&g_cnt[(gid / NN) * GC + cell_of(x, y, z)], 1);
        }
        int r = gid & 3;
        unsigned m1 = __ballot_sync(0xFFFFFFFFu, act && (r == 1) && mb);
        unsigned m2 = __ballot_sync(0xFFFFFFFFu, act && (r >= 2) && mb);
        if ((tid & 31) == 0 && (m1 | m2))
            atomicOr(&g_mtype, (m1 ? 1 : 0) | (m2 ? 2 : 0));
    }
    gridbar();

    // phase 2: per-batch exclusive scan (blocks 0,1)
    if (bid < BB) {
        __shared__ int part[NTHRP];
        int base = bid * GC + tid * 16;
        int loc[16]; int s = 0;
#pragma unroll
        for (int k = 0; k < 16; k++) { loc[k] = s; s += g_cnt[base + k]; }
        part[tid] = s;
        __syncthreads();
        for (int d = 1; d < NTHRP; d <<= 1) {
            int v = (tid >= d) ? part[tid - d] : 0;
            __syncthreads();
            part[tid] += v;
            __syncthreads();
        }
        int off = part[tid] - s;
#pragma unroll
        for (int k = 0; k < 16; k++) {
            int st = off + loc[k];
            g_range[base + k] = make_int2(st, st + g_cnt[base + k]);
            g_cur[base + k]   = st;
        }
    }
    gridbar();

    // phase 3: scatter + masked centroid
    if (gid < NPT) {
        int mt = g_mtype;
        float x = pts[gid * 3 + 0], y = pts[gid * 3 + 1], z = pts[gid * 3 + 2];
        float sq = __fadd_rn(__fadd_rn(__fmul_rn(x, x), __fmul_rn(y, y)), __fmul_rn(z, z));
        int b = gid / NN;
        int cell = b * GC + cell_of(x, y, z);
        bool mk = read_mask(mask, gid, mt);
        float wv = mk ? __uint_as_float(__float_as_uint(sq) | 0x80000000u) : sq;
        int pos = atomicAdd(&g_cur[cell], 1);
        int dst = b * NN + pos;
        g_sp4[dst]  = make_float4(x, y, z, wv);
        g_sidx[dst] = gid;
        double vx = mk ? (double)x : 0.0, vy = mk ? (double)y : 0.0;
        double vz = mk ? (double)z : 0.0, vc = mk ? 1.0 : 0.0;
#pragma unroll
        for (int o = 16; o > 0; o >>= 1) {
            vx += __shfl_down_sync(0xFFFFFFFFu, vx, o);
            vy += __shfl_down_sync(0xFFFFFFFFu, vy, o);
            vz += __shfl_down_sync(0xFFFFFFFFu, vz, o);
            vc += __shfl_down_sync(0xFFFFFFFFu, vc, o);
        }
        if ((tid & 31) == 0) {
            atomicAdd(&g_cacc[b][0], vx);
            atomicAdd(&g_cacc[b][1], vy);
            atomicAdd(&g_cacc[b][2], vz);
            atomicAdd(&g_cacc[b][3], vc);
        }
    }
}

// ---------------- analytic eigenvalues of symmetric 3x3 (fp64) ----------------
__device__ __forceinline__ float curv_from_cov(float c00, float c01, float c02,
                                               float c11, float c12, float c22) {
    double a00 = c00, a01 = c01, a02 = c02, a11 = c11, a12 = c12, a22 = c22;
    double p1 = a01 * a01 + a02 * a02 + a12 * a12;
    double q  = (a00 + a11 + a22) / 3.0;
    double d0 = a00 - q, d1 = a11 - q, d2v = a22 - q;
    double p2 = d0 * d0 + d1 * d1 + d2v * d2v + 2.0 * p1;
    double emin, emax;
    if (!(p2 > 0.0)) { emin = q; emax = q; }
    else {
        double p = sqrt(p2 / 6.0);
        double ip = 1.0 / p;
        double b00 = d0 * ip, b11 = d1 * ip, b22 = d2v * ip;
        double b01 = a01 * ip, b02 = a02 * ip, b12 = a12 * ip;
        double detB = b00 * (b11 * b22 - b12 * b12)
                    - b01 * (b01 * b22 - b12 * b02)
                    + b02 * (b01 * b12 - b11 * b02);
        double r = 0.5 * detB;
        r = fmin(1.0, fmax(-1.0, r));
        double phi = acos(r) / 3.0;
        emax = q + 2.0 * p * cos(phi);
        emin = q + 2.0 * p * cos(phi + 2.0943951023931953);
    }
    float e0 = (float)emin, e2 = (float)emax;
    return e0 / (e2 + 1e-8f);
}

// ================= kernel 2: 8-lane cooperative exact 10-NN + density =================
__global__ void __launch_bounds__(256) k_geom2() {
    const int gt = blockIdx.x * 256 + threadIdx.x;   // 131072 threads
    const int p  = gt >> 3;
    const int l8 = gt & 7;
    const int b  = p >> 13;
    const int s  = p & (NN - 1);
    const int boff  = b * NN;
    const int cbase = b * GC;
    const unsigned gmask = 0xFFu << ((threadIdx.x & 31) & ~7);

    float4 pi = g_sp4[boff + s];
    const float pix = pi.x, piy = pi.y, piz = pi.z, piw = fabsf(pi.w);
    const int orig  = g_sidx[boff + s];
    const float Tloc = g_T;

    const int cix = min(GRID - 1, max(0, (int)(pix * (float)GRID)));
    const int ciy = min(GRID - 1, max(0, (int)(piy * (float)GRID)));
    const int ciz = min(GRID - 1, max(0, (int)(piz * (float)GRID)));

    // per-point kNN radius estimate: ~22 expected neighbors, wall-clip aware
    float r_est = 0.075f;
#pragma unroll
    for (int it = 0; it < 2; it++) {
        float fx = (fminf(pix + r_est, 1.0f) - fmaxf(pix - r_est, 0.0f)) / (2.0f * r_est);
        float fy = (fminf(piy + r_est, 1.0f) - fmaxf(piy - r_est, 0.0f)) / (2.0f * r_est);
        float fz = (fminf(piz + r_est, 1.0f) - fmaxf(piz - r_est, 0.0f)) / (2.0f * r_est);
        r_est = cbrtf(6.4e-4f / fmaxf(fx * fy * fz, 0.125f));
    }
    const float t_est = r_est * r_est;
    const unsigned long long GATE_EST =
        ((unsigned long long)__float_as_uint(t_est) << 32) | 0xFFFFFFFFull;
    const unsigned long long GATE_INF = 0xFFFFFFFFFFFFFFFFull;

    unsigned long long best[KNN];
    int cnt;
    float c00, c01, c02, c11, c12, c22;
    unsigned long long d10key;

    for (int R = 2;; R++) {
        unsigned long long ginit = (R == 2) ? GATE_EST : GATE_INF;

        for (;;) {   // attempt loop (gate verify / retry)
#pragma unroll
            for (int k = 0; k < KNN; k++) best[k] = ginit;
            cnt = 0;
            int passes = 0;

            const int W = 2 * R + 1;
            const int nr = W * W;
            const int x0 = max(cix - R, 0), x1 = min(cix + R, GRID - 1);
            int qy = l8, qz = 0;
            while (qy >= W) { qy -= W; qz++; }

            for (int q = l8; q < nr; q += 8) {
                int zz = ciz + qz - R, yy = ciy + qy - R;
                if ((unsigned)zz < GRID && (unsigned)yy < GRID) {
                    int crow = cbase + (zz * GRID + yy) * GRID;
                    int jst = g_range[crow + x0].x;
                    int jen = g_range[crow + x1].y;
                    for (int j = jst; j < jen; ++j) {
                        float4 pj = g_sp4[boff + j];
                        float sqj = fabsf(pj.w);
                        float Tv  = (__float_as_uint(pj.w) & 0x80000000u)
                                    ? Tloc : __int_as_float(0xff800000);
                        float dot = fmaf(pix, pj.x, fmaf(piy, pj.y, piz * pj.z));
                        float d2  = fmaf(-2.0f, dot, piw + sqj);
                        if (d2 <= Tv) cnt++;
                        float d2c = fmaxf(d2, 0.0f);
                        if (d2c < t_est) passes++;
                        unsigned long long key =
                            ((unsigned long long)__float_as_uint(d2c) << 32) | (unsigned)j;
                        if (key < best[KNN - 1]) {
#pragma unroll
                            for (int k = 0; k < KNN; k++) {
                                if (key < best[k]) {
                                    unsigned long long tmp = best[k]; best[k] = key; key = tmp;
                                }
                            }
                        }
                    }
                }
                qy += 8;
                while (qy >= W) { qy -= W; qz++; }
            }

            if (ginit == GATE_INF) break;          // exhaustive scan, no verify needed
            int pall = passes;
            pall += __shfl_xor_sync(gmask, pall, 1);
            pall += __shfl_xor_sync(gmask, pall, 2);
            pall += __shfl_xor_sync(gmask, pall, 4);
            if (pall >= KNN) break;                // gate verified: true top-10 captured
            ginit = GATE_INF;                      // rare: rescan ungated
        }

        // merge top-10 across the 8 lanes; owner pops + accumulates covariance
        c00 = c01 = c02 = c11 = c12 = c22 = 0.0f;
        d10key = GATE_INF;
#pragma unroll
        for (int round = 0; round < KNN; round++) {
            unsigned long long m = best[0];
            m = min(m, __shfl_xor_sync(gmask, m, 1));
            m = min(m, __shfl_xor_sync(gmask, m, 2));
            m = min(m, __shfl_xor_sync(gmask, m, 4));
            bool real = ((unsigned)(m & 0xFFFFFFFFull)) != 0xFFFFFFFFu;
            if (m == best[0] && real) {
                int j = (int)(unsigned)(m & 0xFFFFFFFFull);
                float4 q = g_sp4[boff + j];
                float dx = q.x - pix, dy = q.y - piy, dz = q.z - piz;
                c00 = fmaf(dx, dx, c00); c01 = fmaf(dx, dy, c01); c02 = fmaf(dx, dz, c02);
                c11 = fmaf(dy, dy, c11); c12 = fmaf(dy, dz, c12); c22 = fmaf(dz, dz, c22);
#pragma unroll
                for (int k = 0; k < KNN - 1; k++) best[k] = best[k + 1];
                best[KNN - 1] = GATE_INF;
            }
            d10key = m;
        }

        // exactness: 10th dist must beat distance to scanned-box walls (domain edges free)
        float g = __int_as_float(0x7f800000);
        if (cix - R > 0)        g = fminf(g, pix - (float)(cix - R) * HCELL);
        if (cix + R < GRID - 1) g = fminf(g, (float)(cix + R + 1) * HCELL - pix);
        if (ciy - R > 0)        g = fminf(g, piy - (float)(ciy - R) * HCELL);
        if (ciy + R < GRID - 1) g = fminf(g, (float)(ciy + R + 1) * HCELL - piy);
        if (ciz - R > 0)        g = fminf(g, piz - (float)(ciz - R) * HCELL);
        if (ciz + R < GRID - 1) g = fminf(g, (float)(ciz + R + 1) * HCELL - piz);
        bool filled = ((unsigned)(d10key & 0xFFFFFFFFull)) != 0xFFFFFFFFu;
        float d10 = __uint_as_float((unsigned)(d10key >> 32));
        if (filled && d10 < g * g) break;
        if (R >= GRID) break;
    }

    // reduce density + covariance across the 8 lanes
#pragma unroll
    for (int o = 1; o < 8; o <<= 1) {
        cnt += __shfl_xor_sync(gmask, cnt, o);
        c00 += __shfl_xor_sync(gmask, c00, o);
        c01 += __shfl_xor_sync(gmask, c01, o);
        c02 += __shfl_xor_sync(gmask, c02, o);
        c11 += __shfl_xor_sync(gmask, c11, o);
        c12 += __shfl_xor_sync(gmask, c12, o);
        c22 += __shfl_xor_sync(gmask, c22, o);
    }

    if (l8 == 0) {
        c00 = __fdiv_rn(c00, 10.0f); c01 = __fdiv_rn(c01, 10.0f); c02 = __fdiv_rn(c02, 10.0f);
        c11 = __fdiv_rn(c11, 10.0f); c12 = __fdiv_rn(c12, 10.0f); c22 = __fdiv_rn(c22, 10.0f);
        float curv = curv_from_cov(c00, c01, c02, c11, c12, c22);

        double cm   = g_cacc[b][3];
        double cden = cm > 1.0 ? cm : 1.0;
        float cx = (float)(g_cacc[b][0] / cden);
        float cy = (float)(g_cacc[b][1] / cden);
        float cz = (float)(g_cacc[b][2] / cden);
        float rx = pix - cx, ry = piy - cy, rz = piz - cz;
        float distc = __fsqrt_rn(__fadd_rn(__fadd_rn(__fmul_rn(rx, rx), __fmul_rn(ry, ry)), __fmul_rn(rz, rz)));
        float horiz = __fsqrt_rn(__fadd_rn(__fmul_rn(rx, rx), __fmul_rn(ry, ry)));
        float rad   = atan2f(ry, rx);

        bool valid = cm > 0.0;
        g_geom[orig * 6 + 0] = valid ? distc : 0.0f;
        g_geom[orig * 6 + 1] = valid ? rz    : 0.0f;
        g_geom[orig * 6 + 2] = valid ? horiz : 0.0f;
        g_geom[orig * 6 + 3] = valid ? (float)cnt : 0.0f;
        g_geom[orig * 6 + 4] = valid ? curv  : 0.0f;
        g_geom[orig * 6 + 5] = valid ? rad   : 0.0f;
    }
}

// ================= kernel 3: fused 2-layer MLP (f32x2 FMA) =================
__global__ void __launch_bounds__(256) k_mlp(const float* __restrict__ feat,
                                             const float* __restrict__ W1,
                                             const float* __restrict__ b1,
                                             const float* __restrict__ W2,
                                             const float* __restrict__ b2,
                                             float* __restrict__ out) {
    extern __shared__ float sm[];
    float* sW1 = sm;             // 70*128
    float* sB1 = sm + 8960;
    float* sW2 = sm + 9088;      // 128*128
    float* sB2 = sm + 25472;
    float* sX  = sm + 25600;     // 128*72
    float* sH  = sm + 34816;     // 128*132

    int tid = threadIdx.x;
    for (int i = tid; i < 8960;  i += 256) sW1[i] = W1[i];
    for (int i = tid; i < 16384; i += 256) sW2[i] = W2[i];
    if (tid < 128) { sB1[tid] = b1[tid]; sB2[tid] = b2[tid]; }

    int m0 = blockIdx.x * 128;
    for (int i = tid; i < 128 * 64; i += 256) {
        int r = i >> 6, c = i & 63;
        sX[r * 72 + c] = feat[(m0 + r) * 64 + c];
    }
    for (int i = tid; i < 128 * 6; i += 256) {
        int r = i / 6, c = i % 6;
        sX[r * 72 + 64 + c] = g_geom[(m0 + r) * 6 + c];
    }
    __syncthreads();

    int cg = tid & 31;
    int rg = tid >> 5;

    unsigned long long acc[16][2];
#pragma unroll
    for (int r = 0; r < 16; r++) { acc[r][0] = 0ull; acc[r][1] = 0ull; }

    for (int k = 0; k < 70; k++) {
        ulonglong2 w2 = *(const ulonglong2*)(sW1 + k * 128 + cg * 4);
#pragma unroll
        for (int r = 0; r < 16; r++) {
            unsigned long long xp = pack2(sX[(rg * 16 + r) * 72 + k]);
            FMA2(acc[r][0], w2.x, xp);
            FMA2(acc[r][1], w2.y, xp);
        }
    }
    {
        float4 bv = *(const float4*)(sB1 + cg * 4);
#pragma unroll
        for (int r = 0; r < 16; r++) {
            float a0, a1, a2, a3;
            unpack2(acc[r][0], a0, a1);
            unpack2(acc[r][1], a2, a3);
            float4 h;
            h.x = fmaxf(a0 + bv.x, 0.0f);
            h.y = fmaxf(a1 + bv.y, 0.0f);
            h.z = fmaxf(a2 + bv.z, 0.0f);
            h.w = fmaxf(a3 + bv.w, 0.0f);
            *(float4*)(sH + (rg * 16 + r) * 132 + cg * 4) = h;
        }
    }
    __syncthreads();

#pragma unroll
    for (int r = 0; r < 16; r++) { acc[r][0] = 0ull; acc[r][1] = 0ull; }

    for (int k = 0; k < 128; k++) {
        ulonglong2 w2 = *(const ulonglong2*)(sW2 + k * 128 + cg * 4);
#pragma unroll
        for (int r = 0; r < 16; r++) {
            unsigned long long hp = pack2(sH[(rg * 16 + r) * 132 + k]);
            FMA2(acc[r][0], w2.x, hp);
            FMA2(acc[r][1], w2.y, hp);
        }
    }
    {
        float4 bv = *(const float4*)(sB2 + cg * 4);
#pragma unroll
        for (int r = 0; r < 16; r++) {
            float a0, a1, a2, a3;
            unpack2(acc[r][0], a0, a1);
            unpack2(acc[r][1], a2, a3);
            float4 o;
            o.x = fmaxf(a0 + bv.x, 0.0f);
            o.y = fmaxf(a1 + bv.y, 0.0f);
            o.z = fmaxf(a2 + bv.z, 0.0f);
            o.w = fmaxf(a3 + bv.w, 0.0f);
            *(float4*)(out + (size_t)(m0 + rg * 16 + r) * 128 + cg * 4) = o;
        }
    }
}

// ---------------- launch ----------------
extern "C" void kernel_launch(void* const* d_in, const int* in_sizes, int n_in,
                              void* d_out, int out_size) {
    const float* points = (const float*)d_in[0];
    const float* feat   = (const float*)d_in[1];
    const void*  mask   = d_in[2];
    const float* W1     = (const float*)d_in[3];
    const float* b1     = (const float*)d_in[4];
    const float* W2     = (const float*)d_in[5];
    const float* b2     = (const float*)d_in[6];
    float* out = (float*)d_out;

    cudaFuncSetAttribute(k_mlp, cudaFuncAttributeMaxDynamicSharedMemorySize, 212992);

    k_prep <<<NBLKP, NTHRP>>>(points, mask);
    k_geom2<<<(NPT * 8) / 256, 256>>>();
    k_mlp  <<<NPT / 128, 256, 206848>>>(feat, W1, b1, W2, b2, out);
}